// round 13
// baseline (speedup 1.0000x reference)
#include <cuda_runtime.h>
#include <cstdint>

#define NN 50000
#define NE 800000
#define SD 128
#define NG 128
#define NC 41
#define BN_EPS 1e-5f
#define TM 64
#define TILES 782
#define GRID2 296

typedef unsigned int u32;
typedef unsigned short u16;

// ---------------- scratch (static device globals; no runtime alloc) -------
__device__ float g_xa[NN * SD];
__device__ float g_xb[NN * SD];
__device__ int   g_deg[NN];
__device__ int   g_rowptr[NN + 1];
__device__ int   g_cursor[NN];
__device__ int   g_csrsrc[NE];
__device__ int   g_bsum[64];
__device__ int   g_tick[8];
__device__ float g_pool[NG * SD];
__device__ float g_bnsc[SD];
__device__ float g_bnoff[SD];

// combined bf16 hi/lo W fragments: uint4 per (ks,nt,lane) = (h0,h1,l0,l1)
#define WFU4 4096
__device__ __align__(16) uint4 g_wf[4 * WFU4];

// ---------------- bf16 split helpers --------------------------------------
__device__ __forceinline__ u32 f2bf(float f) {
    u32 u = __float_as_uint(f);
    return (u + 0x7fffu + ((u >> 16) & 1u)) >> 16;
}
__device__ __forceinline__ u32 packsplit(float v) {
    u32 h = f2bf(v);
    float hv = __uint_as_float(h << 16);
    u32 l = f2bf(v - hv);
    return h | (l << 16);
}
__device__ __forceinline__ u32 prmt(u32 a, u32 b, u32 s) {
    u32 d; asm("prmt.b32 %0,%1,%2,%3;" : "=r"(d) : "r"(a), "r"(b), "r"(s)); return d;
}
__device__ __forceinline__ void mma16816(float* c, const u32* a, const u32* b) {
    asm volatile(
        "mma.sync.aligned.m16n8k16.row.col.f32.bf16.bf16.f32 "
        "{%0,%1,%2,%3}, {%4,%5,%6,%7}, {%8,%9}, {%0,%1,%2,%3};"
        : "+f"(c[0]), "+f"(c[1]), "+f"(c[2]), "+f"(c[3])
        : "r"(a[0]), "r"(a[1]), "r"(a[2]), "r"(a[3]), "r"(b[0]), "r"(b[1]));
}

// ---------------- prep: W split + embed + hist + BN fold (one launch) ------
__global__ void k_prep(const int* __restrict__ dst, const float* __restrict__ W0,
                       const float* __restrict__ W1, const float* __restrict__ W2,
                       const float* __restrict__ W3, const int* __restrict__ ids,
                       const float* __restrict__ emb,
                       const float* __restrict__ gamma, const float* __restrict__ beta,
                       const float* __restrict__ mean, const float* __restrict__ var) {
    int b = blockIdx.x, tid = threadIdx.x;
    if (b < 256) {                       // W split: 4*16384 elems
        int t = b * 256 + tid;
        int m = t >> 14, r = t & 16383, n = r >> 7, k = r & 127;
        const float* W = (m == 0) ? W0 : (m == 1) ? W1 : (m == 2) ? W2 : W3;
        float v = W[n * 128 + k];
        u32 h = f2bf(v);
        u32 l = f2bf(v - __uint_as_float(h << 16));
        int ks = k >> 4, nt = n >> 3, kl = k & 15;
        int lane = ((n & 7) << 2) | ((kl >> 1) & 3);
        int f = (ks * 16 + nt) * 32 + lane;
        int reg = kl >> 3, half = kl & 1;
        u16* base = (u16*)(g_wf + (long)m * WFU4 + f);
        base[reg * 2 + half]     = (u16)h;
        base[4 + reg * 2 + half] = (u16)l;
    } else if (b < 256 + 6250) {         // embed copy: NN*32 float4
        int t = (b - 256) * 256 + tid;
        if (t < NN * 32) {
            int n = t >> 5, q = t & 31;
            ((float4*)g_xa)[n * 32 + q] =
                __ldg((const float4*)emb + (long)__ldg(ids + n) * 32 + q);
        }
    } else if (b < 256 + 6250 + 3125) {  // degree hist
        int e = (b - 6506) * 256 + tid;
        if (e < NE) atomicAdd(&g_deg[dst[e]], 1);
    } else {                             // BN fold
        if (tid < SD) {
            float sc = gamma[tid] * rsqrtf(var[tid] + BN_EPS);
            g_bnsc[tid] = sc;
            g_bnoff[tid] = beta[tid] - mean[tid] * sc;
        }
    }
}

// ---------------- 3-phase scan: block scans + tiny scan + fixup ------------
__global__ void k_scan1() {
    __shared__ int ws[32];
    int tid = threadIdx.x, lane = tid & 31, wid = tid >> 5;
    int i = blockIdx.x * 1024 + tid;
    int v = (i < NN) ? g_deg[i] : 0;
    int s = v;
#pragma unroll
    for (int d = 1; d < 32; d <<= 1) {
        int t = __shfl_up_sync(0xffffffffu, s, d);
        if (lane >= d) s += t;
    }
    if (lane == 31) ws[wid] = s;
    __syncthreads();
    if (wid == 0) {
        int t = ws[lane];
#pragma unroll
        for (int d = 1; d < 32; d <<= 1) {
            int u = __shfl_up_sync(0xffffffffu, t, d);
            if (lane >= d) t += u;
        }
        ws[lane] = t;
    }
    __syncthreads();
    int excl = (wid ? ws[wid - 1] : 0) + s - v;
    if (i < NN) g_rowptr[i] = excl;
    if (tid == 1023) g_bsum[blockIdx.x] = excl + v;
}
__global__ void k_scan2() {   // 64 threads, scans 49 block sums (exclusive)
    int t = threadIdx.x;
    int v = (t < 49) ? g_bsum[t] : 0;
    int s = v;
#pragma unroll
    for (int d = 1; d < 32; d <<= 1) {
        int u = __shfl_up_sync(0xffffffffu, s, d);
        if ((t & 31) >= d) s += u;
    }
    __shared__ int w0;
    if (t == 31) w0 = s;
    __syncthreads();
    if (t >= 32) s += w0;
    if (t < 49) g_bsum[t] = s - v;
    if (t == 48) g_rowptr[NN] = s;
}
__global__ void k_scan3() {
    int i = blockIdx.x * 1024 + threadIdx.x;
    if (i < NN) {
        int r = g_rowptr[i] + g_bsum[blockIdx.x];
        g_rowptr[i] = r;
        g_cursor[i] = r;
    }
}
__global__ void k_csr(const int* __restrict__ src, const int* __restrict__ dst) {
    int e = blockIdx.x * blockDim.x + threadIdx.x;
    if (e < NE) {
        int p = atomicAdd(&g_cursor[dst[e]], 1);
        g_csrsrc[p] = src[e];
    }
}

// ---------------- GEMM pass: warp owns 1 m-tile (16 rows) x 32 cols --------
__device__ __forceinline__ void gemm_pass(
    const u32* sA, const uint4* wf, int wm, int wn, int lane, float acc[4][4])
{
#pragma unroll
    for (int n = 0; n < 4; n++)
#pragma unroll
        for (int j = 0; j < 4; j++) acc[n][j] = 0.f;

    const int row0 = wm + (lane >> 2);
    const int row1 = row0 + 8;
    const int sw0 = (row0 & 7) << 2;
    const int sw1 = (row1 & 7) << 2;

#pragma unroll
    for (int ks = 0; ks < 8; ks++) {
        int kp0 = ks * 8 + (lane & 3);
        int kp1 = kp0 + 4;
        uint2 p00 = *(const uint2*)(sA + (row0 * 64 + (kp0 ^ sw0)) * 2);
        uint2 p10 = *(const uint2*)(sA + (row1 * 64 + (kp0 ^ sw1)) * 2);
        uint2 p01 = *(const uint2*)(sA + (row0 * 64 + (kp1 ^ sw0)) * 2);
        uint2 p11 = *(const uint2*)(sA + (row1 * 64 + (kp1 ^ sw1)) * 2);
        u32 ah[4], al[4];
        ah[0] = prmt(p00.x, p00.y, 0x5410); al[0] = prmt(p00.x, p00.y, 0x7632);
        ah[1] = prmt(p10.x, p10.y, 0x5410); al[1] = prmt(p10.x, p10.y, 0x7632);
        ah[2] = prmt(p01.x, p01.y, 0x5410); al[2] = prmt(p01.x, p01.y, 0x7632);
        ah[3] = prmt(p11.x, p11.y, 0x5410); al[3] = prmt(p11.x, p11.y, 0x7632);
#pragma unroll
        for (int n = 0; n < 4; n++) {
            int nt = (wn >> 3) + n;
            uint4 w = __ldg(wf + (ks * 16 + nt) * 32 + lane);
            const u32* bh = (const u32*)&w;
            const u32* bl = bh + 2;
            mma16816(acc[n], ah, bh);
            mma16816(acc[n], ah, bl);
            mma16816(acc[n], al, bh);
        }
    }
}

// ---------------- fused layer: 64-row tiles, dynamic fetch -----------------
template <int BN_MODE>
__global__ void __launch_bounds__(512, 2) k_layer(
    const float* __restrict__ X, float* __restrict__ Xout,
    const uint4* __restrict__ wf1, const float* __restrict__ b1,
    const uint4* __restrict__ wf2, const float* __restrict__ b2,
    int* __restrict__ tick)
{
    extern __shared__ __align__(16) u32 sA[];   // 64 * 64 * 2 u32 = 32KB
    __shared__ int s_t;
    const int tid  = threadIdx.x;
    const int lane = tid & 31;
    const int wid  = tid >> 5;                  // 0..15
    const int wm   = (wid & 3) * 16;            // m-tile base row (0..48)
    const int wn   = (wid >> 2) * 32;           // n group (0,32,64,96)
    const float4* x4 = (const float4*)X;

    while (true) {
        __syncthreads();                        // sA reuse + s_t protection
        if (tid == 0) s_t = atomicAdd(tick, 1);
        __syncthreads();
        const int t = s_t;
        if (t >= TILES) return;
        const int r0 = t * TM;

        // ---- Phase A: aggregation y = x_self + sum_neigh, into SMEM ----
#pragma unroll 1
        for (int q = 0; q < 4; q++) {
            int nd = r0 + wid * 4 + q;
            if (nd >= NN) break;
            float4 s = __ldg(x4 + (long)nd * 32 + lane);
            int e = g_rowptr[nd], end = g_rowptr[nd + 1];
            for (; e + 4 <= end; e += 4) {
                int j0 = __ldg(&g_csrsrc[e]);
                int j1 = __ldg(&g_csrsrc[e + 1]);
                int j2 = __ldg(&g_csrsrc[e + 2]);
                int j3 = __ldg(&g_csrsrc[e + 3]);
                float4 a = __ldg(x4 + (long)j0 * 32 + lane);
                float4 b = __ldg(x4 + (long)j1 * 32 + lane);
                float4 c = __ldg(x4 + (long)j2 * 32 + lane);
                float4 d = __ldg(x4 + (long)j3 * 32 + lane);
                s.x += (a.x + b.x) + (c.x + d.x);
                s.y += (a.y + b.y) + (c.y + d.y);
                s.z += (a.z + b.z) + (c.z + d.z);
                s.w += (a.w + b.w) + (c.w + d.w);
            }
            for (; e < end; e++) {
                float4 a = __ldg(x4 + (long)__ldg(&g_csrsrc[e]) * 32 + lane);
                s.x += a.x; s.y += a.y; s.z += a.z; s.w += a.w;
            }
            int row = nd - r0;
            int g = row * 64 + ((lane * 2) ^ ((row & 7) << 2));
            uint4 o;
            o.x = packsplit(s.x); o.y = packsplit(s.y);
            o.z = packsplit(s.z); o.w = packsplit(s.w);
            *(uint4*)(sA + g * 2) = o;
        }
        __syncthreads();

        // ---- Phase B: h = relu(y@W1 + b1), re-split into SMEM ----
        float acc[4][4];
        gemm_pass(sA, wf1, wm, wn, lane, acc);
        __syncthreads();
        {
            int row0 = wm + (lane >> 2);
            int row1 = row0 + 8;
#pragma unroll
            for (int n = 0; n < 4; n++) {
                int col = wn + n * 8 + (lane & 3) * 2;
                float bb0 = __ldg(&b1[col]), bb1 = __ldg(&b1[col + 1]);
                float v0 = fmaxf(acc[n][0] + bb0, 0.f);
                float v1 = fmaxf(acc[n][1] + bb1, 0.f);
                float v2 = fmaxf(acc[n][2] + bb0, 0.f);
                float v3 = fmaxf(acc[n][3] + bb1, 0.f);
                int kp = col >> 1;
                int g0 = row0 * 64 + (kp ^ ((row0 & 7) << 2));
                int g1 = row1 * 64 + (kp ^ ((row1 & 7) << 2));
                *(uint2*)(sA + g0 * 2) = make_uint2(packsplit(v0), packsplit(v1));
                *(uint2*)(sA + g1 * 2) = make_uint2(packsplit(v2), packsplit(v3));
            }
        }
        __syncthreads();

        // ---- Phase C: x = [bn](relu(h@W2 + b2)) -> global f32 ----
        gemm_pass(sA, wf2, wm, wn, lane, acc);
        {
            int row0 = wm + (lane >> 2);
#pragma unroll
            for (int n = 0; n < 4; n++) {
                int col = wn + n * 8 + (lane & 3) * 2;
                float bb0 = __ldg(&b2[col]), bb1 = __ldg(&b2[col + 1]);
                float sc0 = 1.f, sc1 = 1.f, of0 = 0.f, of1 = 0.f;
                if (BN_MODE) {
                    sc0 = g_bnsc[col];  sc1 = g_bnsc[col + 1];
                    of0 = g_bnoff[col]; of1 = g_bnoff[col + 1];
                }
#pragma unroll
                for (int h = 0; h < 2; h++) {
                    int r = r0 + row0 + h * 8;
                    if (r < NN) {
                        float z0 = fmaxf(acc[n][h * 2 + 0] + bb0, 0.f);
                        float z1 = fmaxf(acc[n][h * 2 + 1] + bb1, 0.f);
                        if (BN_MODE) {
                            z0 = z0 * sc0 + of0;
                            z1 = z1 * sc1 + of1;
                        }
                        *(float2*)(Xout + (long)r * 128 + col) = make_float2(z0, z1);
                    }
                }
            }
        }
    }
}

// ---------------- pooling (batch sorted -> run-length accumulate) ----------
#define NODES_PB 250
__global__ void k_pool(const float* __restrict__ X, const int* __restrict__ batch) {
    int c = threadIdx.x;
    int n0 = blockIdx.x * NODES_PB;
    int n1 = n0 + NODES_PB;
    if (n1 > NN) n1 = NN;
    if (n0 >= NN) return;
    float acc = 0.f;
    int cur = batch[n0];
    for (int n = n0; n < n1; n++) {
        int b = __ldg(&batch[n]);
        float v = X[(long)n * SD + c];
        if (b != cur) {
            atomicAdd(&g_pool[cur * SD + c], acc);
            acc = 0.f; cur = b;
        }
        acc += v;
    }
    atomicAdd(&g_pool[cur * SD + c], acc);
}

// ---------------- tiny FC head ---------------------------------------------
__global__ void k_fc(const float* __restrict__ fc1W, const float* __restrict__ fc1b,
                     const float* __restrict__ fc2W, const float* __restrict__ fc2b,
                     float* __restrict__ out) {
    __shared__ float p[SD];
    __shared__ float h[SD];
    int g = blockIdx.x, t = threadIdx.x;
    p[t] = g_pool[g * SD + t];
    __syncthreads();
    float s = fc1b[t];
#pragma unroll 8
    for (int k = 0; k < SD; k++) s += p[k] * fc1W[t * SD + k];
    h[t] = fmaxf(s, 0.f);
    __syncthreads();
    if (t < NC) {
        float s2 = fc2b[t];
#pragma unroll 8
        for (int k = 0; k < SD; k++) s2 += h[k] * fc2W[t * SD + k];
        out[g * NC + t] = s2;
    }
}

// ---------------- launch ---------------------------------------------------
#define SM_LAYER (8192 * 4)

extern "C" void kernel_launch(void* const* d_in, const int* in_sizes, int n_in,
                              void* d_out, int out_size) {
    const int*   node_ids = (const int*)d_in[0];
    const int*   edge     = (const int*)d_in[1];
    const int*   batch    = (const int*)d_in[2];
    const float* emb      = (const float*)d_in[3];
    const float* in_W1    = (const float*)d_in[4];
    const float* in_b1    = (const float*)d_in[5];
    const float* in_W2    = (const float*)d_in[6];
    const float* in_b2    = (const float*)d_in[7];
    const float* bn_gamma = (const float*)d_in[8];
    const float* bn_beta  = (const float*)d_in[9];
    const float* bn_mean  = (const float*)d_in[10];
    const float* bn_var   = (const float*)d_in[11];
    const float* out_W1   = (const float*)d_in[12];
    const float* out_b1   = (const float*)d_in[13];
    const float* out_W2   = (const float*)d_in[14];
    const float* out_b2   = (const float*)d_in[15];
    const float* fc1_W    = (const float*)d_in[16];
    const float* fc1_b    = (const float*)d_in[17];
    const float* fc2_W    = (const float*)d_in[18];
    const float* fc2_b    = (const float*)d_in[19];
    float* out = (float*)d_out;

    const int* src = edge;
    const int* dst = edge + NE;

    float *p_xa, *p_xb, *p_pool;
    int *p_deg, *p_tick;
    uint4* p_wf;
    cudaGetSymbolAddress((void**)&p_xa, g_xa);
    cudaGetSymbolAddress((void**)&p_xb, g_xb);
    cudaGetSymbolAddress((void**)&p_pool, g_pool);
    cudaGetSymbolAddress((void**)&p_deg, g_deg);
    cudaGetSymbolAddress((void**)&p_tick, g_tick);
    cudaGetSymbolAddress((void**)&p_wf, g_wf);

    cudaFuncSetAttribute(k_layer<0>, cudaFuncAttributeMaxDynamicSharedMemorySize, SM_LAYER);
    cudaFuncSetAttribute(k_layer<1>, cudaFuncAttributeMaxDynamicSharedMemorySize, SM_LAYER);

    cudaMemsetAsync(p_deg, 0, NN * sizeof(int));
    cudaMemsetAsync(p_pool, 0, NG * SD * sizeof(float));
    cudaMemsetAsync(p_tick, 0, 8 * sizeof(int));

    // prep (W split + embed copy + degree hist + BN fold), scan x3, csr
    k_prep<<<9632, 256>>>(dst, in_W1, in_W2, out_W1, out_W2, node_ids, emb,
                          bn_gamma, bn_beta, bn_mean, bn_var);
    k_scan1<<<49, 1024>>>();
    k_scan2<<<1, 64>>>();
    k_scan3<<<49, 1024>>>();
    k_csr<<<(NE + 255) / 256, 256>>>(src, dst);

    // six fused layers (dynamic tile fetch over 296 persistent CTAs)
    float* cur = p_xa;
    float* nxt = p_xb;
    for (int L = 0; L < 6; L++) {
        if (L < 5)
            k_layer<1><<<GRID2, 512, SM_LAYER>>>(cur, nxt,
                p_wf, in_b1, p_wf + WFU4, in_b2, p_tick + L);
        else
            k_layer<0><<<GRID2, 512, SM_LAYER>>>(cur, nxt,
                p_wf + 2 * WFU4, out_b1, p_wf + 3 * WFU4, out_b2, p_tick + L);
        float* t = cur; cur = nxt; nxt = t;
    }
    // result in `cur`

    k_pool<<<(NN + NODES_PB - 1) / NODES_PB, 128>>>(cur, batch);
    k_fc<<<NG, 128>>>(fc1_W, fc1_b, fc2_W, fc2_b, out);
}

// round 14
// speedup vs baseline: 1.0836x; 1.0836x over previous
#include <cuda_runtime.h>
#include <cstdint>

#define NN 50000
#define NE 800000
#define SD 128
#define NG 128
#define NC 41
#define BN_EPS 1e-5f
#define TM 64
#define TILES 782

typedef unsigned int u32;
typedef unsigned short u16;

// ---------------- scratch (static device globals; no runtime alloc) -------
__device__ float g_xa[NN * SD];
__device__ float g_xb[NN * SD];
__device__ int   g_deg[NN];
__device__ int   g_rowptr[NN + 1];
__device__ int   g_cursor[NN];
__device__ int   g_csrsrc[NE];
__device__ int   g_bsum[64];
__device__ float g_pool[NG * SD];
__device__ float g_bnsc[SD];
__device__ float g_bnoff[SD];

// combined bf16 hi/lo W fragments: uint4 per (ks,nt,lane) = (h0,h1,l0,l1)
#define WFU4 4096
__device__ __align__(16) uint4 g_wf[4 * WFU4];

// ---------------- bf16 split helpers --------------------------------------
__device__ __forceinline__ u32 f2bf(float f) {
    u32 u = __float_as_uint(f);
    return (u + 0x7fffu + ((u >> 16) & 1u)) >> 16;
}
__device__ __forceinline__ u32 packsplit(float v) {
    u32 h = f2bf(v);
    float hv = __uint_as_float(h << 16);
    u32 l = f2bf(v - hv);
    return h | (l << 16);
}
__device__ __forceinline__ u32 prmt(u32 a, u32 b, u32 s) {
    u32 d; asm("prmt.b32 %0,%1,%2,%3;" : "=r"(d) : "r"(a), "r"(b), "r"(s)); return d;
}
__device__ __forceinline__ void mma16816(float* c, const u32* a, const u32* b) {
    asm volatile(
        "mma.sync.aligned.m16n8k16.row.col.f32.bf16.bf16.f32 "
        "{%0,%1,%2,%3}, {%4,%5,%6,%7}, {%8,%9}, {%0,%1,%2,%3};"
        : "+f"(c[0]), "+f"(c[1]), "+f"(c[2]), "+f"(c[3])
        : "r"(a[0]), "r"(a[1]), "r"(a[2]), "r"(a[3]), "r"(b[0]), "r"(b[1]));
}

// ---------------- prep: W split + embed + hist + BN fold (one launch) ------
__global__ void k_prep(const int* __restrict__ dst, const float* __restrict__ W0,
                       const float* __restrict__ W1, const float* __restrict__ W2,
                       const float* __restrict__ W3, const int* __restrict__ ids,
                       const float* __restrict__ emb,
                       const float* __restrict__ gamma, const float* __restrict__ beta,
                       const float* __restrict__ mean, const float* __restrict__ var) {
    int b = blockIdx.x, tid = threadIdx.x;
    if (b < 256) {                       // W split: 4*16384 elems
        int t = b * 256 + tid;
        int m = t >> 14, r = t & 16383, n = r >> 7, k = r & 127;
        const float* W = (m == 0) ? W0 : (m == 1) ? W1 : (m == 2) ? W2 : W3;
        float v = W[n * 128 + k];
        u32 h = f2bf(v);
        u32 l = f2bf(v - __uint_as_float(h << 16));
        int ks = k >> 4, nt = n >> 3, kl = k & 15;
        int lane = ((n & 7) << 2) | ((kl >> 1) & 3);
        int f = (ks * 16 + nt) * 32 + lane;
        int reg = kl >> 3, half = kl & 1;
        u16* base = (u16*)(g_wf + (long)m * WFU4 + f);
        base[reg * 2 + half]     = (u16)h;
        base[4 + reg * 2 + half] = (u16)l;
    } else if (b < 256 + 6250) {         // embed copy: NN*32 float4
        int t = (b - 256) * 256 + tid;
        if (t < NN * 32) {
            int n = t >> 5, q = t & 31;
            ((float4*)g_xa)[n * 32 + q] =
                __ldg((const float4*)emb + (long)__ldg(ids + n) * 32 + q);
        }
    } else if (b < 256 + 6250 + 3125) {  // degree hist
        int e = (b - 6506) * 256 + tid;
        if (e < NE) atomicAdd(&g_deg[dst[e]], 1);
    } else {                             // BN fold
        if (tid < SD) {
            float sc = gamma[tid] * rsqrtf(var[tid] + BN_EPS);
            g_bnsc[tid] = sc;
            g_bnoff[tid] = beta[tid] - mean[tid] * sc;
        }
    }
}

// ---------------- 3-phase scan: block scans + tiny scan + fixup ------------
__global__ void k_scan1() {
    __shared__ int ws[32];
    int tid = threadIdx.x, lane = tid & 31, wid = tid >> 5;
    int i = blockIdx.x * 1024 + tid;
    int v = (i < NN) ? g_deg[i] : 0;
    int s = v;
#pragma unroll
    for (int d = 1; d < 32; d <<= 1) {
        int t = __shfl_up_sync(0xffffffffu, s, d);
        if (lane >= d) s += t;
    }
    if (lane == 31) ws[wid] = s;
    __syncthreads();
    if (wid == 0) {
        int t = ws[lane];
#pragma unroll
        for (int d = 1; d < 32; d <<= 1) {
            int u = __shfl_up_sync(0xffffffffu, t, d);
            if (lane >= d) t += u;
        }
        ws[lane] = t;
    }
    __syncthreads();
    int excl = (wid ? ws[wid - 1] : 0) + s - v;
    if (i < NN) g_rowptr[i] = excl;
    if (tid == 1023) g_bsum[blockIdx.x] = excl + v;
}
__global__ void k_scan2() {   // 64 threads, scans 49 block sums (exclusive)
    int t = threadIdx.x;
    int v = (t < 49) ? g_bsum[t] : 0;
    int s = v;
#pragma unroll
    for (int d = 1; d < 32; d <<= 1) {
        int u = __shfl_up_sync(0xffffffffu, s, d);
        if ((t & 31) >= d) s += u;
    }
    __shared__ int w0;
    if (t == 31) w0 = s;
    __syncthreads();
    if (t >= 32) s += w0;
    if (t < 49) g_bsum[t] = s - v;
    if (t == 48) g_rowptr[NN] = s;
}
__global__ void k_scan3() {
    int i = blockIdx.x * 1024 + threadIdx.x;
    if (i < NN) {
        int r = g_rowptr[i] + g_bsum[blockIdx.x];
        g_rowptr[i] = r;
        g_cursor[i] = r;
    }
}
__global__ void k_csr(const int* __restrict__ src, const int* __restrict__ dst) {
    int e = blockIdx.x * blockDim.x + threadIdx.x;
    if (e < NE) {
        int p = atomicAdd(&g_cursor[dst[e]], 1);
        g_csrsrc[p] = src[e];
    }
}

// ---------------- GEMM pass: warp owns 1 m-tile (16 rows) x 32 cols --------
__device__ __forceinline__ void gemm_pass(
    const u32* sA, const uint4* wf, int wm, int wn, int lane, float acc[4][4])
{
#pragma unroll
    for (int n = 0; n < 4; n++)
#pragma unroll
        for (int j = 0; j < 4; j++) acc[n][j] = 0.f;

    const int row0 = wm + (lane >> 2);
    const int row1 = row0 + 8;
    const int sw0 = (row0 & 7) << 2;
    const int sw1 = (row1 & 7) << 2;

#pragma unroll
    for (int ks = 0; ks < 8; ks++) {
        int kp0 = ks * 8 + (lane & 3);
        int kp1 = kp0 + 4;
        uint2 p00 = *(const uint2*)(sA + (row0 * 64 + (kp0 ^ sw0)) * 2);
        uint2 p10 = *(const uint2*)(sA + (row1 * 64 + (kp0 ^ sw1)) * 2);
        uint2 p01 = *(const uint2*)(sA + (row0 * 64 + (kp1 ^ sw0)) * 2);
        uint2 p11 = *(const uint2*)(sA + (row1 * 64 + (kp1 ^ sw1)) * 2);
        u32 ah[4], al[4];
        ah[0] = prmt(p00.x, p00.y, 0x5410); al[0] = prmt(p00.x, p00.y, 0x7632);
        ah[1] = prmt(p10.x, p10.y, 0x5410); al[1] = prmt(p10.x, p10.y, 0x7632);
        ah[2] = prmt(p01.x, p01.y, 0x5410); al[2] = prmt(p01.x, p01.y, 0x7632);
        ah[3] = prmt(p11.x, p11.y, 0x5410); al[3] = prmt(p11.x, p11.y, 0x7632);
#pragma unroll
        for (int n = 0; n < 4; n++) {
            int nt = (wn >> 3) + n;
            uint4 w = __ldg(wf + (ks * 16 + nt) * 32 + lane);
            const u32* bh = (const u32*)&w;
            const u32* bl = bh + 2;
            mma16816(acc[n], ah, bh);
            mma16816(acc[n], ah, bl);
            mma16816(acc[n], al, bh);
        }
    }
}

// ---------------- fused layer: 64-row tiles, static grid, dual buffer ------
template <int BN_MODE>
__global__ void __launch_bounds__(512, 2) k_layer(
    const float* __restrict__ X, float* __restrict__ Xout,
    const uint4* __restrict__ wf1, const float* __restrict__ b1,
    const uint4* __restrict__ wf2, const float* __restrict__ b2)
{
    extern __shared__ __align__(16) u32 smem[];   // 2 x 8192 u32 = 64KB
    u32* sA = smem;            // aggregated input y
    u32* sB = smem + 8192;     // hidden h
    const int tid  = threadIdx.x;
    const int lane = tid & 31;
    const int wid  = tid >> 5;                  // 0..15
    const int r0   = blockIdx.x * TM;
    const int wm   = (wid & 3) * 16;            // m-tile base row (0..48)
    const int wn   = (wid >> 2) * 32;           // n group (0,32,64,96)

    // ---- Phase A: aggregation y = x_self + sum_neigh, into sA ----
    const float4* x4 = (const float4*)X;
#pragma unroll 1
    for (int q = 0; q < 4; q++) {
        int nd = r0 + wid * 4 + q;
        if (nd >= NN) break;
        float4 s = __ldg(x4 + (long)nd * 32 + lane);
        int e = g_rowptr[nd], end = g_rowptr[nd + 1];
        for (; e + 4 <= end; e += 4) {
            int j0 = __ldg(&g_csrsrc[e]);
            int j1 = __ldg(&g_csrsrc[e + 1]);
            int j2 = __ldg(&g_csrsrc[e + 2]);
            int j3 = __ldg(&g_csrsrc[e + 3]);
            float4 a = __ldg(x4 + (long)j0 * 32 + lane);
            float4 b = __ldg(x4 + (long)j1 * 32 + lane);
            float4 c = __ldg(x4 + (long)j2 * 32 + lane);
            float4 d = __ldg(x4 + (long)j3 * 32 + lane);
            s.x += (a.x + b.x) + (c.x + d.x);
            s.y += (a.y + b.y) + (c.y + d.y);
            s.z += (a.z + b.z) + (c.z + d.z);
            s.w += (a.w + b.w) + (c.w + d.w);
        }
        for (; e < end; e++) {
            float4 a = __ldg(x4 + (long)__ldg(&g_csrsrc[e]) * 32 + lane);
            s.x += a.x; s.y += a.y; s.z += a.z; s.w += a.w;
        }
        int row = nd - r0;
        int g = row * 64 + ((lane * 2) ^ ((row & 7) << 2));
        uint4 o;
        o.x = packsplit(s.x); o.y = packsplit(s.y);
        o.z = packsplit(s.z); o.w = packsplit(s.w);
        *(uint4*)(sA + g * 2) = o;
    }
    __syncthreads();

    // ---- Phase B: h = relu(y@W1 + b1) -> sB (no read/write hazard) ----
    float acc[4][4];
    gemm_pass(sA, wf1, wm, wn, lane, acc);
    {
        int row0 = wm + (lane >> 2);
        int row1 = row0 + 8;
#pragma unroll
        for (int n = 0; n < 4; n++) {
            int col = wn + n * 8 + (lane & 3) * 2;
            float bb0 = __ldg(&b1[col]), bb1 = __ldg(&b1[col + 1]);
            float v0 = fmaxf(acc[n][0] + bb0, 0.f);
            float v1 = fmaxf(acc[n][1] + bb1, 0.f);
            float v2 = fmaxf(acc[n][2] + bb0, 0.f);
            float v3 = fmaxf(acc[n][3] + bb1, 0.f);
            int kp = col >> 1;
            int g0 = row0 * 64 + (kp ^ ((row0 & 7) << 2));
            int g1 = row1 * 64 + (kp ^ ((row1 & 7) << 2));
            *(uint2*)(sB + g0 * 2) = make_uint2(packsplit(v0), packsplit(v1));
            *(uint2*)(sB + g1 * 2) = make_uint2(packsplit(v2), packsplit(v3));
        }
    }
    __syncthreads();

    // ---- Phase C: x = [bn](relu(h@W2 + b2)) -> global f32 ----
    gemm_pass(sB, wf2, wm, wn, lane, acc);
    {
        int row0 = wm + (lane >> 2);
#pragma unroll
        for (int n = 0; n < 4; n++) {
            int col = wn + n * 8 + (lane & 3) * 2;
            float bb0 = __ldg(&b2[col]), bb1 = __ldg(&b2[col + 1]);
            float sc0 = 1.f, sc1 = 1.f, of0 = 0.f, of1 = 0.f;
            if (BN_MODE) {
                sc0 = g_bnsc[col];  sc1 = g_bnsc[col + 1];
                of0 = g_bnoff[col]; of1 = g_bnoff[col + 1];
            }
#pragma unroll
            for (int h = 0; h < 2; h++) {
                int r = r0 + row0 + h * 8;
                if (r < NN) {
                    float z0 = fmaxf(acc[n][h * 2 + 0] + bb0, 0.f);
                    float z1 = fmaxf(acc[n][h * 2 + 1] + bb1, 0.f);
                    if (BN_MODE) {
                        z0 = z0 * sc0 + of0;
                        z1 = z1 * sc1 + of1;
                    }
                    *(float2*)(Xout + (long)r * 128 + col) = make_float2(z0, z1);
                }
            }
        }
    }
}

// ---------------- pooling (batch sorted -> run-length accumulate) ----------
#define NODES_PB 250
__global__ void k_pool(const float* __restrict__ X, const int* __restrict__ batch) {
    int c = threadIdx.x;
    int n0 = blockIdx.x * NODES_PB;
    int n1 = n0 + NODES_PB;
    if (n1 > NN) n1 = NN;
    if (n0 >= NN) return;
    float acc = 0.f;
    int cur = batch[n0];
    for (int n = n0; n < n1; n++) {
        int b = __ldg(&batch[n]);
        float v = X[(long)n * SD + c];
        if (b != cur) {
            atomicAdd(&g_pool[cur * SD + c], acc);
            acc = 0.f; cur = b;
        }
        acc += v;
    }
    atomicAdd(&g_pool[cur * SD + c], acc);
}

// ---------------- tiny FC head ---------------------------------------------
__global__ void k_fc(const float* __restrict__ fc1W, const float* __restrict__ fc1b,
                     const float* __restrict__ fc2W, const float* __restrict__ fc2b,
                     float* __restrict__ out) {
    __shared__ float p[SD];
    __shared__ float h[SD];
    int g = blockIdx.x, t = threadIdx.x;
    p[t] = g_pool[g * SD + t];
    __syncthreads();
    float s = fc1b[t];
#pragma unroll 8
    for (int k = 0; k < SD; k++) s += p[k] * fc1W[t * SD + k];
    h[t] = fmaxf(s, 0.f);
    __syncthreads();
    if (t < NC) {
        float s2 = fc2b[t];
#pragma unroll 8
        for (int k = 0; k < SD; k++) s2 += h[k] * fc2W[t * SD + k];
        out[g * NC + t] = s2;
    }
}

// ---------------- launch ---------------------------------------------------
#define SM_LAYER (2 * 8192 * 4)

extern "C" void kernel_launch(void* const* d_in, const int* in_sizes, int n_in,
                              void* d_out, int out_size) {
    const int*   node_ids = (const int*)d_in[0];
    const int*   edge     = (const int*)d_in[1];
    const int*   batch    = (const int*)d_in[2];
    const float* emb      = (const float*)d_in[3];
    const float* in_W1    = (const float*)d_in[4];
    const float* in_b1    = (const float*)d_in[5];
    const float* in_W2    = (const float*)d_in[6];
    const float* in_b2    = (const float*)d_in[7];
    const float* bn_gamma = (const float*)d_in[8];
    const float* bn_beta  = (const float*)d_in[9];
    const float* bn_mean  = (const float*)d_in[10];
    const float* bn_var   = (const float*)d_in[11];
    const float* out_W1   = (const float*)d_in[12];
    const float* out_b1   = (const float*)d_in[13];
    const float* out_W2   = (const float*)d_in[14];
    const float* out_b2   = (const float*)d_in[15];
    const float* fc1_W    = (const float*)d_in[16];
    const float* fc1_b    = (const float*)d_in[17];
    const float* fc2_W    = (const float*)d_in[18];
    const float* fc2_b    = (const float*)d_in[19];
    float* out = (float*)d_out;

    const int* src = edge;
    const int* dst = edge + NE;

    float *p_xa, *p_xb, *p_pool;
    int* p_deg;
    uint4* p_wf;
    cudaGetSymbolAddress((void**)&p_xa, g_xa);
    cudaGetSymbolAddress((void**)&p_xb, g_xb);
    cudaGetSymbolAddress((void**)&p_pool, g_pool);
    cudaGetSymbolAddress((void**)&p_deg, g_deg);
    cudaGetSymbolAddress((void**)&p_wf, g_wf);

    cudaFuncSetAttribute(k_layer<0>, cudaFuncAttributeMaxDynamicSharedMemorySize, SM_LAYER);
    cudaFuncSetAttribute(k_layer<1>, cudaFuncAttributeMaxDynamicSharedMemorySize, SM_LAYER);

    cudaMemsetAsync(p_deg, 0, NN * sizeof(int));
    cudaMemsetAsync(p_pool, 0, NG * SD * sizeof(float));

    // prep (W split + embed copy + degree hist + BN fold), scan x3, csr
    k_prep<<<9632, 256>>>(dst, in_W1, in_W2, out_W1, out_W2, node_ids, emb,
                          bn_gamma, bn_beta, bn_mean, bn_var);
    k_scan1<<<49, 1024>>>();
    k_scan2<<<1, 64>>>();
    k_scan3<<<49, 1024>>>();
    k_csr<<<(NE + 255) / 256, 256>>>(src, dst);

    // six fused layers (static grid; HW work-steals wave >= 2)
    float* cur = p_xa;
    float* nxt = p_xb;
    for (int L = 0; L < 6; L++) {
        if (L < 5)
            k_layer<1><<<TILES, 512, SM_LAYER>>>(cur, nxt,
                p_wf, in_b1, p_wf + WFU4, in_b2);
        else
            k_layer<0><<<TILES, 512, SM_LAYER>>>(cur, nxt,
                p_wf + 2 * WFU4, out_b1, p_wf + 3 * WFU4, out_b2);
        float* t = cur; cur = nxt; nxt = t;
    }
    // result in `cur`

    k_pool<<<(NN + NODES_PB - 1) / NODES_PB, 128>>>(cur, batch);
    k_fc<<<NG, 128>>>(fc1_W, fc1_b, fc2_W, fc2_b, out);
}